// round 4
// baseline (speedup 1.0000x reference)
#include <cuda_runtime.h>
#include <cuda_bf16.h>
#include <cstdint>

#define BATCH 64
#define CIN   384
#define COUT  384
#define NEXP  8
#define HW    784

// Is tcgen05 available in this device-code pass? (arch- or family-specific only)
#if defined(__CUDA_ARCH__) && (defined(__CUDA_ARCH_FEAT_SM103_ALL) || \
    defined(__CUDA_ARCH_FEAT_SM100_ALL) || defined(__CUDA_ARCH_SPECIFIC__) || \
    defined(__CUDA_ARCH_FAMILY_SPECIFIC__))
#define HAS_TCGEN05 1
#else
#define HAS_TCGEN05 0
#endif

// ---------------- device scratch ----------------
__device__ __align__(16) __nv_bfloat16 g_a_hi[BATCH * COUT * CIN];
__device__ __align__(16) __nv_bfloat16 g_a_lo[BATCH * COUT * CIN];
__device__ __align__(16) float         g_a_f32[BATCH * COUT * CIN];  // fallback path
__device__ __align__(16) __nv_bfloat16 g_x_hi[BATCH * HW * CIN];     // transposed [b][hw][cin]
__device__ __align__(16) __nv_bfloat16 g_x_lo[BATCH * HW * CIN];

// ---------------------------------------------------------------------------
// Kernel 1: split + transpose x:  xT_hi/lo[b][n][k] = split(x[b][k][n])
// ---------------------------------------------------------------------------
__global__ __launch_bounds__(256)
void split_x_kernel(const float* __restrict__ x,
                    __nv_bfloat16* __restrict__ xh,
                    __nv_bfloat16* __restrict__ xl)
{
    __shared__ float t[32][33];
    const int b  = blockIdx.z;
    const int k0 = blockIdx.y * 32;
    const int n0 = blockIdx.x * 32;
    const float* xb = x + (size_t)b * CIN * HW;

#pragma unroll
    for (int j = 0; j < 4; j++) {
        int k = k0 + threadIdx.y + j * 8;
        int n = n0 + threadIdx.x;
        t[threadIdx.y + j * 8][threadIdx.x] = (n < HW) ? xb[(size_t)k * HW + n] : 0.f;
    }
    __syncthreads();

    __nv_bfloat16* oh = xh + (size_t)b * HW * CIN;
    __nv_bfloat16* ol = xl + (size_t)b * HW * CIN;
#pragma unroll
    for (int j = 0; j < 4; j++) {
        int n = n0 + threadIdx.y + j * 8;
        int k = k0 + threadIdx.x;
        if (n < HW) {
            float v = t[threadIdx.x][threadIdx.y + j * 8];
            __nv_bfloat16 h = __float2bfloat16(v);
            __nv_bfloat16 l = __float2bfloat16(v - __bfloat162float(h));
            oh[(size_t)n * CIN + k] = h;
            ol[(size_t)n * CIN + k] = l;
        }
    }
}

// ---------------------------------------------------------------------------
// Kernel 2: agg[b,o,i] = sum_e rw[b,e]*w[e,o,i]  ->  bf16 hi/lo (+ fp32 copy)
// ---------------------------------------------------------------------------
__global__ __launch_bounds__(256)
void agg_kernel(const float* __restrict__ rw, const float* __restrict__ w,
                __nv_bfloat16* __restrict__ ah, __nv_bfloat16* __restrict__ al,
                float* __restrict__ af)
{
    __shared__ float s_rw[BATCH * NEXP];
    const int tid = threadIdx.x;
    for (int i = tid; i < BATCH * NEXP; i += blockDim.x) s_rw[i] = rw[i];
    __syncthreads();

    const int oi = blockIdx.x * blockDim.x + tid;
    if (oi >= COUT * CIN) return;

    float we[NEXP];
#pragma unroll
    for (int e = 0; e < NEXP; e++) we[e] = w[e * (COUT * CIN) + oi];

#pragma unroll 4
    for (int b = 0; b < BATCH; b++) {
        float acc = 0.f;
#pragma unroll
        for (int e = 0; e < NEXP; e++) acc = fmaf(s_rw[b * NEXP + e], we[e], acc);
        __nv_bfloat16 h = __float2bfloat16(acc);
        __nv_bfloat16 l = __float2bfloat16(acc - __bfloat162float(h));
        ah[(size_t)b * (COUT * CIN) + oi] = h;
        al[(size_t)b * (COUT * CIN) + oi] = l;
        af[(size_t)b * (COUT * CIN) + oi] = acc;
    }
}

// ---------------------------------------------------------------------------
// Kernel 3: GEMM.  Per CTA: C[128,112] = agg[128,384] * xT[112,384]^T
// tcgen05 path: 3-term bf16 split, K-chunks of 64, 2-stage SMEM ring.
// Fallback path (non-'a' PTX pass): SIMT fp32 GEMM, same geometry.
// ---------------------------------------------------------------------------
#define TM 128
#define TN 112           // 784 = 7*112
#define KC 64
#define NCHUNK (CIN / KC)  // 6

#define SA_BYTES (TM * 128)
#define SX_BYTES (TN * 128)
#define STAGE_BYTES (2 * SA_BYTES + 2 * SX_BYTES)
#define SM_STAGE0 1024
#define SM_TOTAL (SM_STAGE0 + 2 * STAGE_BYTES)     // 123904

// idesc: F32 accum, BF16 x BF16, K-major both, N=112, M=128
#define IDESC ((1u << 4) | (1u << 7) | (1u << 10) | ((TN / 8) << 17) | ((TM / 16) << 24))

#if HAS_TCGEN05
// ---------------- tcgen05 PTX helpers (compiled only for sm_103a) ----------
__device__ __forceinline__ uint32_t smem_u32(const void* p) {
    uint32_t a;
    asm("{ .reg .u64 t; cvta.to.shared.u64 t, %1; cvt.u32.u64 %0, t; }" : "=r"(a) : "l"(p));
    return a;
}

#define MBARRIER_INIT(addr, cnt) \
    asm volatile("mbarrier.init.shared.b64 [%0], %1;" :: "r"(addr), "r"(cnt) : "memory")

#define MBARRIER_WAIT_PARITY(addr, par) do {                                   \
    uint32_t _m = (addr), _p = (par), _d;                                      \
    asm volatile("{\n\t.reg .pred p;\n\t"                                      \
        "mbarrier.try_wait.parity.acquire.cta.shared::cta.b64 p, [%1], %2;\n\t"\
        "selp.b32 %0, 1, 0, p;\n\t}" : "=r"(_d) : "r"(_m), "r"(_p) : "memory");\
    if (!_d) {                                                                 \
        asm volatile("{\n\t.reg .pred P1;\n\t"                                 \
            "WL_%=:\n\t"                                                       \
            "mbarrier.try_wait.parity.acquire.cta.shared::cta.b64 P1, [%0], %1, 0x989680;\n\t" \
            "@P1 bra.uni WD_%=;\n\t"                                           \
            "bra.uni WL_%=;\n\t"                                               \
            "WD_%=:\n\t}" :: "r"(_m), "r"(_p) : "memory");                     \
    }                                                                          \
} while (0)

#define TCGEN05_ALLOC(sm_res, n) \
    asm volatile("tcgen05.alloc.cta_group::1.sync.aligned.shared::cta.b32 [%0], %1;" \
        :: "r"(sm_res), "r"((uint32_t)(n)) : "memory")
#define TCGEN05_RELINQ() \
    asm volatile("tcgen05.relinquish_alloc_permit.cta_group::1.sync.aligned;")
#define TCGEN05_DEALLOC(t, n) \
    asm volatile("tcgen05.dealloc.cta_group::1.sync.aligned.b32 %0, %1;" :: "r"(t), "r"((uint32_t)(n)))
#define TCGEN05_COMMIT(mbar) \
    asm volatile("tcgen05.commit.cta_group::1.mbarrier::arrive::one.shared::cluster.b64 [%0];" \
        :: "r"(mbar) : "memory")
#define TCGEN05_FENCE_AFTER()  asm volatile("tcgen05.fence::after_thread_sync;" ::: "memory")
#define TCGEN05_FENCE_BEFORE() asm volatile("tcgen05.fence::before_thread_sync;" ::: "memory")
#define TCGEN05_WAIT_LD()      asm volatile("tcgen05.wait::ld.sync.aligned;" ::: "memory")
#define FENCE_ASYNC_SHARED()   asm volatile("fence.proxy.async.shared::cta;" ::: "memory")

__device__ __forceinline__ void mma_f16_ss(uint32_t d, uint64_t a, uint64_t b,
                                           uint32_t idesc, uint32_t en) {
    asm volatile("{\n\t.reg .pred p;\n\t"
        "setp.ne.u32 p, %5, 0;\n\t"
        "tcgen05.mma.cta_group::1.kind::f16 [%0], %1, %2, %3, {%4, %4, %4, %4}, p;\n\t}"
        :: "r"(d), "l"(a), "l"(b), "r"(idesc), "r"(0u), "r"(en) : "memory");
}

static constexpr uint64_t DESC_BASE =
    (uint64_t(2) << 61) | (uint64_t(1) << 46) | (uint64_t(64) << 32) | (uint64_t(1) << 16);
#define MAKE_DESC(a) (DESC_BASE | ((uint64_t)((a) >> 4) & 0x3FFF))

#define LDTM_X32(r, t) \
    asm volatile("tcgen05.ld.sync.aligned.32x32b.x32.b32 " \
        "{%0,%1,%2,%3,%4,%5,%6,%7,%8,%9,%10,%11,%12,%13,%14,%15," \
        "%16,%17,%18,%19,%20,%21,%22,%23,%24,%25,%26,%27,%28,%29,%30,%31}, [%32];" \
        : "=r"((r)[0]),"=r"((r)[1]),"=r"((r)[2]),"=r"((r)[3]),"=r"((r)[4]),"=r"((r)[5]),"=r"((r)[6]),"=r"((r)[7]), \
          "=r"((r)[8]),"=r"((r)[9]),"=r"((r)[10]),"=r"((r)[11]),"=r"((r)[12]),"=r"((r)[13]),"=r"((r)[14]),"=r"((r)[15]), \
          "=r"((r)[16]),"=r"((r)[17]),"=r"((r)[18]),"=r"((r)[19]),"=r"((r)[20]),"=r"((r)[21]),"=r"((r)[22]),"=r"((r)[23]), \
          "=r"((r)[24]),"=r"((r)[25]),"=r"((r)[26]),"=r"((r)[27]),"=r"((r)[28]),"=r"((r)[29]),"=r"((r)[30]),"=r"((r)[31]) \
        : "r"(t))

#define LDTM_X16(r, t) \
    asm volatile("tcgen05.ld.sync.aligned.32x32b.x16.b32 " \
        "{%0,%1,%2,%3,%4,%5,%6,%7,%8,%9,%10,%11,%12,%13,%14,%15}, [%16];" \
        : "=r"((r)[0]),"=r"((r)[1]),"=r"((r)[2]),"=r"((r)[3]),"=r"((r)[4]),"=r"((r)[5]),"=r"((r)[6]),"=r"((r)[7]), \
          "=r"((r)[8]),"=r"((r)[9]),"=r"((r)[10]),"=r"((r)[11]),"=r"((r)[12]),"=r"((r)[13]),"=r"((r)[14]),"=r"((r)[15]) \
        : "r"(t))

__device__ __forceinline__ void copy_tile(const __nv_bfloat16* __restrict__ g,
                                          char* s, int rows, int tid)
{
    const int n4 = rows * 8;  // uint4 (8 bf16) chunks per row of 64 bf16
    for (int i = tid; i < n4; i += 128) {
        int r = i >> 3, q = i & 7;
        uint4 v = *reinterpret_cast<const uint4*>(g + (size_t)r * CIN + q * 8);
        uint32_t off = (uint32_t)(r * 128 + q * 16);
        off ^= (off >> 3) & 0x70;
        *reinterpret_cast<uint4*>(s + off) = v;
    }
}
#endif  // HAS_TCGEN05

__global__ __launch_bounds__(128, 1)
void gemm_kernel(const __nv_bfloat16* __restrict__ ah,
                 const __nv_bfloat16* __restrict__ al,
                 const __nv_bfloat16* __restrict__ xh,
                 const __nv_bfloat16* __restrict__ xl,
                 const float* __restrict__ aggf,
                 const float* __restrict__ x,
                 float* __restrict__ out)
{
    extern __shared__ char smem[];
    const int tid = threadIdx.x;
    const int b  = blockIdx.z;
    const int m0 = blockIdx.y * TM;
    const int n0 = blockIdx.x * TN;

#if HAS_TCGEN05
    (void)aggf; (void)x;
    const uint32_t smem_base = smem_u32(smem);
    const uint32_t mb_empty0 = smem_base + 8;
    const uint32_t mb_empty1 = smem_base + 16;
    const uint32_t mb_done   = smem_base + 24;

    if ((tid >> 5) == 0) TCGEN05_ALLOC(smem_base, 128);
    if (tid == 0) {
        MBARRIER_INIT(mb_empty0, 1);
        MBARRIER_INIT(mb_empty1, 1);
        MBARRIER_INIT(mb_done, 1);
    }
    if ((tid >> 5) == 0) TCGEN05_RELINQ();
    __syncthreads();

    uint32_t tmem_base;
    asm volatile("ld.shared.b32 %0, [%1];" : "=r"(tmem_base) : "r"(smem_base));

    const __nv_bfloat16* gah = ah + ((size_t)b * COUT + m0) * CIN;
    const __nv_bfloat16* gal = al + ((size_t)b * COUT + m0) * CIN;
    const __nv_bfloat16* gxh = xh + ((size_t)b * HW + n0) * CIN;
    const __nv_bfloat16* gxl = xl + ((size_t)b * HW + n0) * CIN;

    {
        char* st = smem + SM_STAGE0;
        copy_tile(gah, st, TM, tid);
        copy_tile(gal, st + SA_BYTES, TM, tid);
        copy_tile(gxh, st + 2 * SA_BYTES, TN, tid);
        copy_tile(gxl, st + 2 * SA_BYTES + SX_BYTES, TN, tid);
    }
    FENCE_ASYNC_SHARED();
    __syncthreads();

    for (int c = 0; c < NCHUNK; c++) {
        const int s = c & 1;
        if (tid == 0) {
            const uint32_t stg = smem_base + SM_STAGE0 + s * STAGE_BYTES;
            const uint64_t dah = MAKE_DESC(stg);
            const uint64_t dal = MAKE_DESC(stg + SA_BYTES);
            const uint64_t dxh = MAKE_DESC(stg + 2 * SA_BYTES);
            const uint64_t dxl = MAKE_DESC(stg + 2 * SA_BYTES + SX_BYTES);
#pragma unroll
            for (int ks = 0; ks < 4; ks++)
                mma_f16_ss(tmem_base, dah + 2 * ks, dxh + 2 * ks, IDESC,
                           (c > 0 || ks > 0) ? 1u : 0u);
#pragma unroll
            for (int ks = 0; ks < 4; ks++)
                mma_f16_ss(tmem_base, dal + 2 * ks, dxh + 2 * ks, IDESC, 1u);
#pragma unroll
            for (int ks = 0; ks < 4; ks++)
                mma_f16_ss(tmem_base, dah + 2 * ks, dxl + 2 * ks, IDESC, 1u);
            if (c <= 3)       TCGEN05_COMMIT(s ? mb_empty1 : mb_empty0);
            else if (c == 5)  TCGEN05_COMMIT(mb_done);
        }
        if (c + 1 < NCHUNK) {
            const int s1 = (c + 1) & 1;
            if (c >= 1)
                MBARRIER_WAIT_PARITY(s1 ? mb_empty1 : mb_empty0, ((c - 1) >> 1) & 1);
            const int k0 = (c + 1) * KC;
            char* st = smem + SM_STAGE0 + s1 * STAGE_BYTES;
            copy_tile(gah + k0, st, TM, tid);
            copy_tile(gal + k0, st + SA_BYTES, TM, tid);
            copy_tile(gxh + k0, st + 2 * SA_BYTES, TN, tid);
            copy_tile(gxl + k0, st + 2 * SA_BYTES + SX_BYTES, TN, tid);
            FENCE_ASYNC_SHARED();
            __syncthreads();
        }
    }

    MBARRIER_WAIT_PARITY(mb_done, 0);
    TCGEN05_FENCE_AFTER();

    const int wid = tid >> 5, lid = tid & 31;
    float* orow = out + ((size_t)b * COUT + m0 + wid * 32 + lid) * HW + n0;

    uint32_t r[32];
    LDTM_X32(r, tmem_base);
    TCGEN05_WAIT_LD();
#pragma unroll
    for (int q = 0; q < 8; q++)
        *reinterpret_cast<float4*>(orow + q * 4) =
            make_float4(__uint_as_float(r[q*4]), __uint_as_float(r[q*4+1]),
                        __uint_as_float(r[q*4+2]), __uint_as_float(r[q*4+3]));
    LDTM_X32(r, tmem_base + 32);
    TCGEN05_WAIT_LD();
#pragma unroll
    for (int q = 0; q < 8; q++)
        *reinterpret_cast<float4*>(orow + 32 + q * 4) =
            make_float4(__uint_as_float(r[q*4]), __uint_as_float(r[q*4+1]),
                        __uint_as_float(r[q*4+2]), __uint_as_float(r[q*4+3]));
    LDTM_X32(r, tmem_base + 64);
    TCGEN05_WAIT_LD();
#pragma unroll
    for (int q = 0; q < 8; q++)
        *reinterpret_cast<float4*>(orow + 64 + q * 4) =
            make_float4(__uint_as_float(r[q*4]), __uint_as_float(r[q*4+1]),
                        __uint_as_float(r[q*4+2]), __uint_as_float(r[q*4+3]));
    LDTM_X16(r, tmem_base + 96);
    TCGEN05_WAIT_LD();
#pragma unroll
    for (int q = 0; q < 4; q++)
        *reinterpret_cast<float4*>(orow + 96 + q * 4) =
            make_float4(__uint_as_float(r[q*4]), __uint_as_float(r[q*4+1]),
                        __uint_as_float(r[q*4+2]), __uint_as_float(r[q*4+3]));

    TCGEN05_FENCE_BEFORE();
    __syncthreads();
    if ((tid >> 5) == 0) TCGEN05_DEALLOC(tmem_base, 128);

#else  // ------------------- SIMT fallback (compute_103 pass) ----------------
    (void)ah; (void)al; (void)xh; (void)xl; (void)smem;
    __shared__ float As[8][TM];    // [k][m]
    __shared__ float Xs[8][TN];    // [k][n]

    const float* A  = aggf + ((size_t)b * COUT + m0) * CIN;
    const float* Xp = x    + (size_t)b * CIN * HW;

    const int ty = tid >> 3;        // 0..15 -> 8 m rows each
    const int tx = tid & 7;         // 0..7  -> 14 n cols each

    float acc[8][14];
#pragma unroll
    for (int i = 0; i < 8; i++)
#pragma unroll
        for (int j = 0; j < 14; j++) acc[i][j] = 0.f;

    for (int k0 = 0; k0 < CIN; k0 += 8) {
        // load A tile: 128 m x 8 k  (1024 elems, 8 per thread)
#pragma unroll
        for (int j = 0; j < 8; j++) {
            int e = tid + 128 * j;
            int m = e >> 3, k = e & 7;
            As[k][m] = A[(size_t)m * CIN + k0 + k];
        }
        // load X tile: 8 k x 112 n  (896 elems, 7 per thread)
#pragma unroll
        for (int j = 0; j < 7; j++) {
            int e = tid + 128 * j;
            int k = e / TN, n = e % TN;
            Xs[k][n] = Xp[(size_t)(k0 + k) * HW + n0 + n];
        }
        __syncthreads();
#pragma unroll
        for (int k = 0; k < 8; k++) {
#pragma unroll
            for (int i = 0; i < 8; i++) {
                float a = As[k][ty * 8 + i];
#pragma unroll
                for (int j = 0; j < 14; j++)
                    acc[i][j] = fmaf(a, Xs[k][tx * 14 + j], acc[i][j]);
            }
        }
        __syncthreads();
    }

#pragma unroll
    for (int i = 0; i < 8; i++) {
        float* orow = out + ((size_t)b * COUT + m0 + ty * 8 + i) * HW + n0 + tx * 14;
#pragma unroll
        for (int j = 0; j < 14; j++) orow[j] = acc[i][j];
    }
#endif
}

// ---------------------------------------------------------------------------
extern "C" void kernel_launch(void* const* d_in, const int* in_sizes, int n_in,
                              void* d_out, int out_size)
{
    const float* x  = (const float*)d_in[0];   // [64, 384, 28, 28]
    const float* rw = (const float*)d_in[1];   // [64, 8]
    const float* w  = (const float*)d_in[2];   // [8, 384, 384]
    float* out = (float*)d_out;

    __nv_bfloat16 *ah, *al, *xh, *xl;
    float* af;
    cudaGetSymbolAddress((void**)&ah, g_a_hi);
    cudaGetSymbolAddress((void**)&al, g_a_lo);
    cudaGetSymbolAddress((void**)&af, g_a_f32);
    cudaGetSymbolAddress((void**)&xh, g_x_hi);
    cudaGetSymbolAddress((void**)&xl, g_x_lo);

    {
        dim3 grid((HW + 31) / 32, CIN / 32, BATCH);
        split_x_kernel<<<grid, dim3(32, 8)>>>(x, xh, xl);
    }
    {
        const int total = COUT * CIN;
        agg_kernel<<<(total + 255) / 256, 256>>>(rw, w, ah, al, af);
    }
    {
        static int smem_set = 0;
        if (!smem_set) {
            cudaFuncSetAttribute(gemm_kernel, cudaFuncAttributeMaxDynamicSharedMemorySize, SM_TOTAL);
            smem_set = 1;
        }
        dim3 grid(HW / TN, COUT / TM, BATCH);   // 7 x 3 x 64
        gemm_kernel<<<grid, 128, SM_TOTAL>>>(ah, al, xh, xl, af, x, out);
    }
}

// round 5
// speedup vs baseline: 7.1585x; 7.1585x over previous
#include <cuda_runtime.h>
#include <cuda_bf16.h>
#include <cstdint>

#define BATCH 64
#define CIN   384
#define COUT  384
#define NEXP  8
#define HW    784
#define NCHUNK 6           // CIN / 64

// Is tcgen05 available in this device-code pass? (arch- or family-specific only)
#if defined(__CUDA_ARCH__) && (defined(__CUDA_ARCH_FEAT_SM103_ALL) || \
    defined(__CUDA_ARCH_FEAT_SM100_ALL) || defined(__CUDA_ARCH_SPECIFIC__) || \
    defined(__CUDA_ARCH_FAMILY_SPECIFIC__))
#define HAS_TCGEN05 1
#else
#define HAS_TCGEN05 0
#endif

// ---------------- device scratch ----------------
// Chunk-major, PRE-SWIZZLED (SW128) layouts so every GEMM tile is one
// contiguous GMEM block:
//   g_a_*: [b][chunk][o(384)][64 bf16]  -> A tile (m0) = 16 KB contiguous
//   g_x_*: [b][chunk][n(784)][64 bf16]  -> X tile (n0) = 14 KB contiguous
__device__ __align__(1024) __nv_bfloat16 g_a_hi[BATCH * NCHUNK * COUT * 64];
__device__ __align__(1024) __nv_bfloat16 g_a_lo[BATCH * NCHUNK * COUT * 64];
__device__ __align__(1024) __nv_bfloat16 g_x_hi[BATCH * NCHUNK * HW * 64];
__device__ __align__(1024) __nv_bfloat16 g_x_lo[BATCH * NCHUNK * HW * 64];
__device__ __align__(16)   float         g_a_f32[BATCH * COUT * CIN];  // fallback only

__device__ __forceinline__ uint32_t sw128(uint32_t off) {
    return off ^ ((off >> 3) & 0x70);
}

// ---------------------------------------------------------------------------
// Kernel 1: split + transpose x into chunk-major swizzled hi/lo
// ---------------------------------------------------------------------------
__global__ __launch_bounds__(256)
void split_x_kernel(const float* __restrict__ x,
                    __nv_bfloat16* __restrict__ xh,
                    __nv_bfloat16* __restrict__ xl)
{
    __shared__ float t[32][33];
    const int b  = blockIdx.z;
    const int k0 = blockIdx.y * 32;
    const int n0 = blockIdx.x * 32;
    const float* xb = x + (size_t)b * CIN * HW;

#pragma unroll
    for (int j = 0; j < 4; j++) {
        int k = k0 + threadIdx.y + j * 8;
        int n = n0 + threadIdx.x;
        t[threadIdx.y + j * 8][threadIdx.x] = (n < HW) ? xb[(size_t)k * HW + n] : 0.f;
    }
    __syncthreads();

    char* xhb = (char*)xh;
    char* xlb = (char*)xl;
#pragma unroll
    for (int j = 0; j < 4; j++) {
        int n = n0 + threadIdx.y + j * 8;
        int k = k0 + threadIdx.x;
        if (n < HW) {
            float v = t[threadIdx.x][threadIdx.y + j * 8];
            __nv_bfloat16 h = __float2bfloat16(v);
            __nv_bfloat16 l = __float2bfloat16(v - __bfloat162float(h));
            int chunk = k >> 6;
            uint32_t local = (uint32_t)(n * 128 + (k & 63) * 2);
            uint32_t sw = sw128(local);
            size_t base = ((size_t)(b * NCHUNK + chunk)) * (HW * 128);
            *reinterpret_cast<__nv_bfloat16*>(xhb + base + sw) = h;
            *reinterpret_cast<__nv_bfloat16*>(xlb + base + sw) = l;
        }
    }
}

// ---------------------------------------------------------------------------
// Kernel 2: agg[b,o,i] = sum_e rw[b,e]*w[e,o,i] -> chunked swizzled bf16 hi/lo
// ---------------------------------------------------------------------------
__global__ __launch_bounds__(256)
void agg_kernel(const float* __restrict__ rw, const float* __restrict__ w,
                __nv_bfloat16* __restrict__ ah, __nv_bfloat16* __restrict__ al,
                float* __restrict__ af)
{
    __shared__ float s_rw[BATCH * NEXP];
    const int tid = threadIdx.x;
    for (int i = tid; i < BATCH * NEXP; i += blockDim.x) s_rw[i] = rw[i];
    __syncthreads();

    const int oi = blockIdx.x * blockDim.x + tid;
    if (oi >= COUT * CIN) return;
    const int o = oi / CIN, i = oi % CIN;
    const int chunk = i >> 6;
    const uint32_t sw = sw128((uint32_t)(o * 128 + (i & 63) * 2));
    const size_t boff = ((size_t)chunk) * (COUT * 128) + sw;

    float we[NEXP];
#pragma unroll
    for (int e = 0; e < NEXP; e++) we[e] = w[e * (COUT * CIN) + oi];

    char* ahb = (char*)ah;
    char* alb = (char*)al;
#pragma unroll 4
    for (int b = 0; b < BATCH; b++) {
        float acc = 0.f;
#pragma unroll
        for (int e = 0; e < NEXP; e++) acc = fmaf(s_rw[b * NEXP + e], we[e], acc);
        __nv_bfloat16 h = __float2bfloat16(acc);
        __nv_bfloat16 l = __float2bfloat16(acc - __bfloat162float(h));
        size_t base = ((size_t)b * NCHUNK) * (COUT * 128) + boff;
        *reinterpret_cast<__nv_bfloat16*>(ahb + base) = h;
        *reinterpret_cast<__nv_bfloat16*>(alb + base) = l;
        af[(size_t)b * (COUT * CIN) + oi] = acc;
    }
}

// ---------------------------------------------------------------------------
// Kernel 3: GEMM.  Per CTA: C[128,112] = agg[128,384] * xT[112,384]^T
// tcgen05 path: bulk-async loads (UBLKCP) + 2-stage ring + 3-term bf16 MMA.
// ---------------------------------------------------------------------------
#define TM 128
#define TN 112           // 784 = 7*112

#define SA_BYTES (TM * 128)                        // 16384
#define SX_BYTES (TN * 128)                        // 14336
#define STAGE_BYTES (2 * SA_BYTES + 2 * SX_BYTES)  // 61440
#define SM_STAGE0 1024
#define SM_TOTAL (SM_STAGE0 + 2 * STAGE_BYTES)     // 123904

// idesc: F32 accum, BF16 x BF16, K-major both, N=112, M=128
#define IDESC ((1u << 4) | (1u << 7) | (1u << 10) | ((TN / 8) << 17) | ((TM / 16) << 24))

#if HAS_TCGEN05
__device__ __forceinline__ uint32_t smem_u32(const void* p) {
    uint32_t a;
    asm("{ .reg .u64 t; cvta.to.shared.u64 t, %1; cvt.u32.u64 %0, t; }" : "=r"(a) : "l"(p));
    return a;
}

#define MBARRIER_INIT(addr, cnt) \
    asm volatile("mbarrier.init.shared.b64 [%0], %1;" :: "r"(addr), "r"(cnt) : "memory")
#define MBARRIER_EXPECT_TX(addr, tx) \
    asm volatile("mbarrier.arrive.expect_tx.shared.b64 _, [%0], %1;" \
        :: "r"(addr), "r"((uint32_t)(tx)) : "memory")

#define MBARRIER_WAIT_PARITY(addr, par) do {                                   \
    uint32_t _m = (addr), _p = (par), _d;                                      \
    asm volatile("{\n\t.reg .pred p;\n\t"                                      \
        "mbarrier.try_wait.parity.acquire.cta.shared::cta.b64 p, [%1], %2;\n\t"\
        "selp.b32 %0, 1, 0, p;\n\t}" : "=r"(_d) : "r"(_m), "r"(_p) : "memory");\
    if (!_d) {                                                                 \
        asm volatile("{\n\t.reg .pred P1;\n\t"                                 \
            "WL_%=:\n\t"                                                       \
            "mbarrier.try_wait.parity.acquire.cta.shared::cta.b64 P1, [%0], %1, 0x989680;\n\t" \
            "@P1 bra.uni WD_%=;\n\t"                                           \
            "bra.uni WL_%=;\n\t"                                               \
            "WD_%=:\n\t}" :: "r"(_m), "r"(_p) : "memory");                     \
    }                                                                          \
} while (0)

#define BULK_G2S(dst, src, bytes, mbar) \
    asm volatile("cp.async.bulk.shared::cluster.global.mbarrier::complete_tx::bytes " \
        "[%0], [%1], %2, [%3];" \
        :: "r"(dst), "l"(src), "r"((uint32_t)(bytes)), "r"(mbar) : "memory")

#define TCGEN05_ALLOC(sm_res, n) \
    asm volatile("tcgen05.alloc.cta_group::1.sync.aligned.shared::cta.b32 [%0], %1;" \
        :: "r"(sm_res), "r"((uint32_t)(n)) : "memory")
#define TCGEN05_RELINQ() \
    asm volatile("tcgen05.relinquish_alloc_permit.cta_group::1.sync.aligned;")
#define TCGEN05_DEALLOC(t, n) \
    asm volatile("tcgen05.dealloc.cta_group::1.sync.aligned.b32 %0, %1;" :: "r"(t), "r"((uint32_t)(n)))
#define TCGEN05_COMMIT(mbar) \
    asm volatile("tcgen05.commit.cta_group::1.mbarrier::arrive::one.shared::cluster.b64 [%0];" \
        :: "r"(mbar) : "memory")
#define TCGEN05_FENCE_AFTER()  asm volatile("tcgen05.fence::after_thread_sync;" ::: "memory")
#define TCGEN05_FENCE_BEFORE() asm volatile("tcgen05.fence::before_thread_sync;" ::: "memory")
#define TCGEN05_WAIT_LD()      asm volatile("tcgen05.wait::ld.sync.aligned;" ::: "memory")

__device__ __forceinline__ void mma_f16_ss(uint32_t d, uint64_t a, uint64_t b,
                                           uint32_t idesc, uint32_t en) {
    asm volatile("{\n\t.reg .pred p;\n\t"
        "setp.ne.u32 p, %5, 0;\n\t"
        "tcgen05.mma.cta_group::1.kind::f16 [%0], %1, %2, %3, {%4, %4, %4, %4}, p;\n\t}"
        :: "r"(d), "l"(a), "l"(b), "r"(idesc), "r"(0u), "r"(en) : "memory");
}

static constexpr uint64_t DESC_BASE =
    (uint64_t(2) << 61) | (uint64_t(1) << 46) | (uint64_t(64) << 32) | (uint64_t(1) << 16);
#define MAKE_DESC(a) (DESC_BASE | ((uint64_t)((a) >> 4) & 0x3FFF))

#define LDTM_X32(r, t) \
    asm volatile("tcgen05.ld.sync.aligned.32x32b.x32.b32 " \
        "{%0,%1,%2,%3,%4,%5,%6,%7,%8,%9,%10,%11,%12,%13,%14,%15," \
        "%16,%17,%18,%19,%20,%21,%22,%23,%24,%25,%26,%27,%28,%29,%30,%31}, [%32];" \
        : "=r"((r)[0]),"=r"((r)[1]),"=r"((r)[2]),"=r"((r)[3]),"=r"((r)[4]),"=r"((r)[5]),"=r"((r)[6]),"=r"((r)[7]), \
          "=r"((r)[8]),"=r"((r)[9]),"=r"((r)[10]),"=r"((r)[11]),"=r"((r)[12]),"=r"((r)[13]),"=r"((r)[14]),"=r"((r)[15]), \
          "=r"((r)[16]),"=r"((r)[17]),"=r"((r)[18]),"=r"((r)[19]),"=r"((r)[20]),"=r"((r)[21]),"=r"((r)[22]),"=r"((r)[23]), \
          "=r"((r)[24]),"=r"((r)[25]),"=r"((r)[26]),"=r"((r)[27]),"=r"((r)[28]),"=r"((r)[29]),"=r"((r)[30]),"=r"((r)[31]) \
        : "r"(t))

#define LDTM_X16(r, t) \
    asm volatile("tcgen05.ld.sync.aligned.32x32b.x16.b32 " \
        "{%0,%1,%2,%3,%4,%5,%6,%7,%8,%9,%10,%11,%12,%13,%14,%15}, [%16];" \
        : "=r"((r)[0]),"=r"((r)[1]),"=r"((r)[2]),"=r"((r)[3]),"=r"((r)[4]),"=r"((r)[5]),"=r"((r)[6]),"=r"((r)[7]), \
          "=r"((r)[8]),"=r"((r)[9]),"=r"((r)[10]),"=r"((r)[11]),"=r"((r)[12]),"=r"((r)[13]),"=r"((r)[14]),"=r"((r)[15]) \
        : "r"(t))
#endif  // HAS_TCGEN05

__global__ __launch_bounds__(128, 1)
void gemm_kernel(const __nv_bfloat16* __restrict__ ah,
                 const __nv_bfloat16* __restrict__ al,
                 const __nv_bfloat16* __restrict__ xh,
                 const __nv_bfloat16* __restrict__ xl,
                 const float* __restrict__ aggf,
                 const float* __restrict__ x,
                 float* __restrict__ out)
{
    extern __shared__ char smem[];
    const int tid = threadIdx.x;
    const int b  = blockIdx.z;
    const int m0 = blockIdx.y * TM;
    const int n0 = blockIdx.x * TN;

#if HAS_TCGEN05
    (void)aggf; (void)x;
    const uint32_t smem_base = smem_u32(smem);
    const uint32_t mb_full0 = smem_base + 8;
    const uint32_t mb_full1 = smem_base + 16;
    const uint32_t mb_mma0  = smem_base + 24;
    const uint32_t mb_mma1  = smem_base + 32;
    const uint32_t mb_done  = smem_base + 40;

    if ((tid >> 5) == 0) TCGEN05_ALLOC(smem_base, 128);
    if (tid == 0) {
        MBARRIER_INIT(mb_full0, 1);
        MBARRIER_INIT(mb_full1, 1);
        MBARRIER_INIT(mb_mma0, 1);
        MBARRIER_INIT(mb_mma1, 1);
        MBARRIER_INIT(mb_done, 1);
    }
    if ((tid >> 5) == 0) TCGEN05_RELINQ();
    __syncthreads();

    uint32_t tmem_base;
    asm volatile("ld.shared.b32 %0, [%1];" : "=r"(tmem_base) : "r"(smem_base));

    if (tid == 0) {
        // GMEM tile bases (chunk-major swizzled layouts)
        const char* gah = (const char*)ah + ((size_t)b * NCHUNK * COUT + m0) * 128;
        const char* gal = (const char*)al + ((size_t)b * NCHUNK * COUT + m0) * 128;
        const char* gxh = (const char*)xh + ((size_t)b * NCHUNK * HW + n0) * 128;
        const char* gxl = (const char*)xl + ((size_t)b * NCHUNK * HW + n0) * 128;
        const size_t a_cstride = (size_t)COUT * 128;  // bytes per chunk block
        const size_t x_cstride = (size_t)HW * 128;

        const uint32_t full[2] = {mb_full0, mb_full1};
        const uint32_t mmad[2] = {mb_mma0, mb_mma1};

        // prologue: load chunks 0 and 1
#pragma unroll
        for (int c = 0; c < 2; c++) {
            const uint32_t stg = smem_base + SM_STAGE0 + c * STAGE_BYTES;
            MBARRIER_EXPECT_TX(full[c], STAGE_BYTES);
            BULK_G2S(stg,                          gah + c * a_cstride, SA_BYTES, full[c]);
            BULK_G2S(stg + SA_BYTES,               gal + c * a_cstride, SA_BYTES, full[c]);
            BULK_G2S(stg + 2 * SA_BYTES,           gxh + c * x_cstride, SX_BYTES, full[c]);
            BULK_G2S(stg + 2 * SA_BYTES + SX_BYTES, gxl + c * x_cstride, SX_BYTES, full[c]);
        }

        for (int c = 0; c < NCHUNK; c++) {
            const int s = c & 1;
            const int par = (c >> 1) & 1;
            MBARRIER_WAIT_PARITY(full[s], par);

            const uint32_t stg = smem_base + SM_STAGE0 + s * STAGE_BYTES;
            const uint64_t dah = MAKE_DESC(stg);
            const uint64_t dal = MAKE_DESC(stg + SA_BYTES);
            const uint64_t dxh = MAKE_DESC(stg + 2 * SA_BYTES);
            const uint64_t dxl = MAKE_DESC(stg + 2 * SA_BYTES + SX_BYTES);
#pragma unroll
            for (int ks = 0; ks < 4; ks++)
                mma_f16_ss(tmem_base, dah + 2 * ks, dxh + 2 * ks, IDESC,
                           (c > 0 || ks > 0) ? 1u : 0u);
#pragma unroll
            for (int ks = 0; ks < 4; ks++)
                mma_f16_ss(tmem_base, dal + 2 * ks, dxh + 2 * ks, IDESC, 1u);
#pragma unroll
            for (int ks = 0; ks < 4; ks++)
                mma_f16_ss(tmem_base, dah + 2 * ks, dxl + 2 * ks, IDESC, 1u);

            if (c == NCHUNK - 1) {
                TCGEN05_COMMIT(mb_done);
            } else {
                TCGEN05_COMMIT(mmad[s]);
                if (c + 2 < NCHUNK) {
                    // reuse stage s for chunk c+2 once its MMAs have drained
                    MBARRIER_WAIT_PARITY(mmad[s], par);
                    MBARRIER_EXPECT_TX(full[s], STAGE_BYTES);
                    const size_t co = (size_t)(c + 2);
                    BULK_G2S(stg,                           gah + co * a_cstride, SA_BYTES, full[s]);
                    BULK_G2S(stg + SA_BYTES,                gal + co * a_cstride, SA_BYTES, full[s]);
                    BULK_G2S(stg + 2 * SA_BYTES,            gxh + co * x_cstride, SX_BYTES, full[s]);
                    BULK_G2S(stg + 2 * SA_BYTES + SX_BYTES, gxl + co * x_cstride, SX_BYTES, full[s]);
                }
            }
        }
    }

    // ---- epilogue (all 4 warps) ----
    MBARRIER_WAIT_PARITY(mb_done, 0);
    TCGEN05_FENCE_AFTER();

    const int wid = tid >> 5, lid = tid & 31;
    float* orow = out + ((size_t)b * COUT + m0 + wid * 32 + lid) * HW + n0;

    uint32_t r[32];
    LDTM_X32(r, tmem_base);
    TCGEN05_WAIT_LD();
#pragma unroll
    for (int q = 0; q < 8; q++)
        *reinterpret_cast<float4*>(orow + q * 4) =
            make_float4(__uint_as_float(r[q*4]), __uint_as_float(r[q*4+1]),
                        __uint_as_float(r[q*4+2]), __uint_as_float(r[q*4+3]));
    LDTM_X32(r, tmem_base + 32);
    TCGEN05_WAIT_LD();
#pragma unroll
    for (int q = 0; q < 8; q++)
        *reinterpret_cast<float4*>(orow + 32 + q * 4) =
            make_float4(__uint_as_float(r[q*4]), __uint_as_float(r[q*4+1]),
                        __uint_as_float(r[q*4+2]), __uint_as_float(r[q*4+3]));
    LDTM_X32(r, tmem_base + 64);
    TCGEN05_WAIT_LD();
#pragma unroll
    for (int q = 0; q < 8; q++)
        *reinterpret_cast<float4*>(orow + 64 + q * 4) =
            make_float4(__uint_as_float(r[q*4]), __uint_as_float(r[q*4+1]),
                        __uint_as_float(r[q*4+2]), __uint_as_float(r[q*4+3]));
    LDTM_X16(r, tmem_base + 96);
    TCGEN05_WAIT_LD();
#pragma unroll
    for (int q = 0; q < 4; q++)
        *reinterpret_cast<float4*>(orow + 96 + q * 4) =
            make_float4(__uint_as_float(r[q*4]), __uint_as_float(r[q*4+1]),
                        __uint_as_float(r[q*4+2]), __uint_as_float(r[q*4+3]));

    TCGEN05_FENCE_BEFORE();
    __syncthreads();
    if ((tid >> 5) == 0) TCGEN05_DEALLOC(tmem_base, 128);

#else  // ------------------- SIMT fallback (compute_103 pass) ----------------
    (void)ah; (void)al; (void)xh; (void)xl; (void)smem;
    __shared__ float As[8][TM];
    __shared__ float Xs[8][TN];

    const float* A  = aggf + ((size_t)b * COUT + m0) * CIN;
    const float* Xp = x    + (size_t)b * CIN * HW;

    const int ty = tid >> 3;
    const int tx = tid & 7;

    float acc[8][14];
#pragma unroll
    for (int i = 0; i < 8; i++)
#pragma unroll
        for (int j = 0; j < 14; j++) acc[i][j] = 0.f;

    for (int k0 = 0; k0 < CIN; k0 += 8) {
#pragma unroll
        for (int j = 0; j < 8; j++) {
            int e = tid + 128 * j;
            int m = e >> 3, k = e & 7;
            As[k][m] = A[(size_t)m * CIN + k0 + k];
        }
#pragma unroll
        for (int j = 0; j < 7; j++) {
            int e = tid + 128 * j;
            int k = e / TN, n = e % TN;
            Xs[k][n] = Xp[(size_t)(k0 + k) * HW + n0 + n];
        }
        __syncthreads();
#pragma unroll
        for (int k = 0; k < 8; k++) {
#pragma unroll
            for (int i = 0; i < 8; i++) {
                float a = As[k][ty * 8 + i];
#pragma unroll
                for (int j = 0; j < 14; j++)
                    acc[i][j] = fmaf(a, Xs[k][tx * 14 + j], acc[i][j]);
            }
        }
        __syncthreads();
    }
#pragma unroll
    for (int i = 0; i < 8; i++) {
        float* orow = out + ((size_t)b * COUT + m0 + ty * 8 + i) * HW + n0 + tx * 14;
#pragma unroll
        for (int j = 0; j < 14; j++) orow[j] = acc[i][j];
    }
#endif
}

// ---------------------------------------------------------------------------
extern "C" void kernel_launch(void* const* d_in, const int* in_sizes, int n_in,
                              void* d_out, int out_size)
{
    const float* x  = (const float*)d_in[0];
    const float* rw = (const float*)d_in[1];
    const float* w  = (const float*)d_in[2];
    float* out = (float*)d_out;

    __nv_bfloat16 *ah, *al, *xh, *xl;
    float* af;
    cudaGetSymbolAddress((void**)&ah, g_a_hi);
    cudaGetSymbolAddress((void**)&al, g_a_lo);
    cudaGetSymbolAddress((void**)&af, g_a_f32);
    cudaGetSymbolAddress((void**)&xh, g_x_hi);
    cudaGetSymbolAddress((void**)&xl, g_x_lo);

    {
        dim3 grid((HW + 31) / 32, CIN / 32, BATCH);
        split_x_kernel<<<grid, dim3(32, 8)>>>(x, xh, xl);
    }
    {
        const int total = COUT * CIN;
        agg_kernel<<<(total + 255) / 256, 256>>>(rw, w, ah, al, af);
    }
    {
        static int smem_set = 0;
        if (!smem_set) {
            cudaFuncSetAttribute(gemm_kernel, cudaFuncAttributeMaxDynamicSharedMemorySize, SM_TOTAL);
            smem_set = 1;
        }
        dim3 grid(HW / TN, COUT / TM, BATCH);   // 7 x 3 x 64
        gemm_kernel<<<grid, 128, SM_TOTAL>>>(ah, al, xh, xl, af, x, out);
    }
}

// round 6
// speedup vs baseline: 8.4756x; 1.1840x over previous
#include <cuda_runtime.h>
#include <cuda_bf16.h>
#include <cstdint>

#define BATCH 64
#define CIN   384
#define COUT  384
#define NEXP  8
#define HW    784
#define KC     32
#define NCHUNK 12          // CIN / KC

// Is tcgen05 available in this device-code pass? (arch- or family-specific only)
#if defined(__CUDA_ARCH__) && (defined(__CUDA_ARCH_FEAT_SM103_ALL) || \
    defined(__CUDA_ARCH_FEAT_SM100_ALL) || defined(__CUDA_ARCH_SPECIFIC__) || \
    defined(__CUDA_ARCH_FAMILY_SPECIFIC__))
#define HAS_TCGEN05 1
#else
#define HAS_TCGEN05 0
#endif

// ---------------- device scratch ----------------
// Chunk-major (KC=32), PRE-SWIZZLED (SW64, 64B rows) layouts:
//   g_a_*: [b][chunk12][o 384][32 bf16]  -> A chunk = 24576 B contiguous
//   g_x_*: [b][chunk12][n 784][32 bf16]  -> X tile (112 rows) = 7168 B contiguous
__device__ __align__(1024) __nv_bfloat16 g_a_hi[BATCH * NCHUNK * COUT * KC];
__device__ __align__(1024) __nv_bfloat16 g_a_lo[BATCH * NCHUNK * COUT * KC];
__device__ __align__(1024) __nv_bfloat16 g_x_hi[BATCH * NCHUNK * HW * KC];
__device__ __align__(1024) __nv_bfloat16 g_x_lo[BATCH * NCHUNK * HW * KC];

__device__ __forceinline__ uint32_t sw64(uint32_t off) {
    return off ^ ((off >> 3) & 0x30);
}

// ---------------------------------------------------------------------------
// Kernel 1: split + transpose x into chunk-major SW64 hi/lo
// ---------------------------------------------------------------------------
__global__ __launch_bounds__(256)
void split_x_kernel(const float* __restrict__ x,
                    __nv_bfloat16* __restrict__ xh,
                    __nv_bfloat16* __restrict__ xl)
{
    __shared__ float t[32][33];
    const int b  = blockIdx.z;
    const int k0 = blockIdx.y * 32;
    const int n0 = blockIdx.x * 32;
    const float* xb = x + (size_t)b * CIN * HW;

#pragma unroll
    for (int j = 0; j < 4; j++) {
        int k = k0 + threadIdx.y + j * 8;
        int n = n0 + threadIdx.x;
        t[threadIdx.y + j * 8][threadIdx.x] = (n < HW) ? xb[(size_t)k * HW + n] : 0.f;
    }
    __syncthreads();

    char* xhb = (char*)xh;
    char* xlb = (char*)xl;
#pragma unroll
    for (int j = 0; j < 4; j++) {
        int n = n0 + threadIdx.y + j * 8;
        int k = k0 + threadIdx.x;
        if (n < HW) {
            float v = t[threadIdx.x][threadIdx.y + j * 8];
            __nv_bfloat16 h = __float2bfloat16(v);
            __nv_bfloat16 l = __float2bfloat16(v - __bfloat162float(h));
            int chunk = k >> 5;
            uint32_t sw = sw64((uint32_t)(n * 64 + (k & 31) * 2));
            size_t base = ((size_t)(b * NCHUNK + chunk)) * (HW * 64);
            *reinterpret_cast<__nv_bfloat16*>(xhb + base + sw) = h;
            *reinterpret_cast<__nv_bfloat16*>(xlb + base + sw) = l;
        }
    }
}

// ---------------------------------------------------------------------------
// Kernel 2: agg[b,o,i] = sum_e rw[b,e]*w[e,o,i] -> chunk-major SW64 bf16 hi/lo
// ---------------------------------------------------------------------------
__global__ __launch_bounds__(256)
void agg_kernel(const float* __restrict__ rw, const float* __restrict__ w,
                __nv_bfloat16* __restrict__ ah, __nv_bfloat16* __restrict__ al)
{
    __shared__ float s_rw[BATCH * NEXP];
    const int tid = threadIdx.x;
    for (int i = tid; i < BATCH * NEXP; i += blockDim.x) s_rw[i] = rw[i];
    __syncthreads();

    const int oi = blockIdx.x * blockDim.x + tid;
    if (oi >= COUT * CIN) return;
    const int o = oi / CIN, i = oi % CIN;
    const int chunk = i >> 5;
    const uint32_t sw = sw64((uint32_t)(o * 64 + (i & 31) * 2));
    const size_t coff = ((size_t)chunk) * (COUT * 64) + sw;

    float we[NEXP];
#pragma unroll
    for (int e = 0; e < NEXP; e++) we[e] = w[e * (COUT * CIN) + oi];

    char* ahb = (char*)ah;
    char* alb = (char*)al;
#pragma unroll 4
    for (int b = 0; b < BATCH; b++) {
        float acc = 0.f;
#pragma unroll
        for (int e = 0; e < NEXP; e++) acc = fmaf(s_rw[b * NEXP + e], we[e], acc);
        __nv_bfloat16 h = __float2bfloat16(acc);
        __nv_bfloat16 l = __float2bfloat16(acc - __bfloat162float(h));
        size_t base = ((size_t)b * NCHUNK) * (COUT * 64) + coff;
        *reinterpret_cast<__nv_bfloat16*>(ahb + base) = h;
        *reinterpret_cast<__nv_bfloat16*>(alb + base) = l;
    }
}

// ---------------------------------------------------------------------------
// Kernel 3: GEMM. Per CTA: C[384,112] for one (b, n-tile).
// 3 M=128 sub-MMAs into TMEM cols {0,112,224}; KC=32 chunks; SW64 operands;
// 3-stage bulk-async ring; 3-term bf16 split.
// ---------------------------------------------------------------------------
#define TN 112                      // 784 = 7*112

#define AT_BYTES (COUT * 64)        // 24576 per A term per chunk (all 384 rows)
#define XT_BYTES (TN * 64)          // 7168 per X term per chunk
#define STAGE_BYTES (2 * AT_BYTES + 2 * XT_BYTES)  // 63488
#define NSTAGE 3
#define SM_STAGE0 1024
#define SM_TOTAL (SM_STAGE0 + NSTAGE * STAGE_BYTES)  // 191488

// idesc: F32 accum, BF16 x BF16, K-major both, N=112, M=128
#define IDESC ((1u << 4) | (1u << 7) | (1u << 10) | ((TN / 8) << 17) | ((128 / 16) << 24))

#if HAS_TCGEN05
__device__ __forceinline__ uint32_t smem_u32(const void* p) {
    uint32_t a;
    asm("{ .reg .u64 t; cvta.to.shared.u64 t, %1; cvt.u32.u64 %0, t; }" : "=r"(a) : "l"(p));
    return a;
}

#define MBARRIER_INIT(addr, cnt) \
    asm volatile("mbarrier.init.shared.b64 [%0], %1;" :: "r"(addr), "r"(cnt) : "memory")
#define MBARRIER_EXPECT_TX(addr, tx) \
    asm volatile("mbarrier.arrive.expect_tx.shared.b64 _, [%0], %1;" \
        :: "r"(addr), "r"((uint32_t)(tx)) : "memory")

#define MBARRIER_WAIT_PARITY(addr, par) do {                                   \
    uint32_t _m = (addr), _p = (par), _d;                                      \
    asm volatile("{\n\t.reg .pred p;\n\t"                                      \
        "mbarrier.try_wait.parity.acquire.cta.shared::cta.b64 p, [%1], %2;\n\t"\
        "selp.b32 %0, 1, 0, p;\n\t}" : "=r"(_d) : "r"(_m), "r"(_p) : "memory");\
    if (!_d) {                                                                 \
        asm volatile("{\n\t.reg .pred P1;\n\t"                                 \
            "WL_%=:\n\t"                                                       \
            "mbarrier.try_wait.parity.acquire.cta.shared::cta.b64 P1, [%0], %1, 0x989680;\n\t" \
            "@P1 bra.uni WD_%=;\n\t"                                           \
            "bra.uni WL_%=;\n\t"                                               \
            "WD_%=:\n\t}" :: "r"(_m), "r"(_p) : "memory");                     \
    }                                                                          \
} while (0)

#define BULK_G2S(dst, src, bytes, mbar) \
    asm volatile("cp.async.bulk.shared::cluster.global.mbarrier::complete_tx::bytes " \
        "[%0], [%1], %2, [%3];" \
        :: "r"(dst), "l"(src), "r"((uint32_t)(bytes)), "r"(mbar) : "memory")

#define TCGEN05_ALLOC(sm_res, n) \
    asm volatile("tcgen05.alloc.cta_group::1.sync.aligned.shared::cta.b32 [%0], %1;" \
        :: "r"(sm_res), "r"((uint32_t)(n)) : "memory")
#define TCGEN05_RELINQ() \
    asm volatile("tcgen05.relinquish_alloc_permit.cta_group::1.sync.aligned;")
#define TCGEN05_DEALLOC(t, n) \
    asm volatile("tcgen05.dealloc.cta_group::1.sync.aligned.b32 %0, %1;" :: "r"(t), "r"((uint32_t)(n)))
#define TCGEN05_COMMIT(mbar) \
    asm volatile("tcgen05.commit.cta_group::1.mbarrier::arrive::one.shared::cluster.b64 [%0];" \
        :: "r"(mbar) : "memory")
#define TCGEN05_FENCE_AFTER()  asm volatile("tcgen05.fence::after_thread_sync;" ::: "memory")
#define TCGEN05_FENCE_BEFORE() asm volatile("tcgen05.fence::before_thread_sync;" ::: "memory")
#define TCGEN05_WAIT_LD()      asm volatile("tcgen05.wait::ld.sync.aligned;" ::: "memory")

__device__ __forceinline__ void mma_f16_ss(uint32_t d, uint64_t a, uint64_t b,
                                           uint32_t idesc, uint32_t en) {
    asm volatile("{\n\t.reg .pred p;\n\t"
        "setp.ne.u32 p, %5, 0;\n\t"
        "tcgen05.mma.cta_group::1.kind::f16 [%0], %1, %2, %3, {%4, %4, %4, %4}, p;\n\t}"
        :: "r"(d), "l"(a), "l"(b), "r"(idesc), "r"(0u), "r"(en) : "memory");
}

// SW64 K-major descriptor: layout=4, version=1, SBO=32 (512B = 8 rows x 64B), LBO=1
static constexpr uint64_t DESC_BASE_SW64 =
    (uint64_t(4) << 61) | (uint64_t(1) << 46) | (uint64_t(32) << 32) | (uint64_t(1) << 16);
#define MAKE_DESC(a) (DESC_BASE_SW64 | ((uint64_t)((a) >> 4) & 0x3FFF))

#define LDTM_X32(r, t) \
    asm volatile("tcgen05.ld.sync.aligned.32x32b.x32.b32 " \
        "{%0,%1,%2,%3,%4,%5,%6,%7,%8,%9,%10,%11,%12,%13,%14,%15," \
        "%16,%17,%18,%19,%20,%21,%22,%23,%24,%25,%26,%27,%28,%29,%30,%31}, [%32];" \
        : "=r"((r)[0]),"=r"((r)[1]),"=r"((r)[2]),"=r"((r)[3]),"=r"((r)[4]),"=r"((r)[5]),"=r"((r)[6]),"=r"((r)[7]), \
          "=r"((r)[8]),"=r"((r)[9]),"=r"((r)[10]),"=r"((r)[11]),"=r"((r)[12]),"=r"((r)[13]),"=r"((r)[14]),"=r"((r)[15]), \
          "=r"((r)[16]),"=r"((r)[17]),"=r"((r)[18]),"=r"((r)[19]),"=r"((r)[20]),"=r"((r)[21]),"=r"((r)[22]),"=r"((r)[23]), \
          "=r"((r)[24]),"=r"((r)[25]),"=r"((r)[26]),"=r"((r)[27]),"=r"((r)[28]),"=r"((r)[29]),"=r"((r)[30]),"=r"((r)[31]) \
        : "r"(t))

#define LDTM_X16(r, t) \
    asm volatile("tcgen05.ld.sync.aligned.32x32b.x16.b32 " \
        "{%0,%1,%2,%3,%4,%5,%6,%7,%8,%9,%10,%11,%12,%13,%14,%15}, [%16];" \
        : "=r"((r)[0]),"=r"((r)[1]),"=r"((r)[2]),"=r"((r)[3]),"=r"((r)[4]),"=r"((r)[5]),"=r"((r)[6]),"=r"((r)[7]), \
          "=r"((r)[8]),"=r"((r)[9]),"=r"((r)[10]),"=r"((r)[11]),"=r"((r)[12]),"=r"((r)[13]),"=r"((r)[14]),"=r"((r)[15]) \
        : "r"(t))
#endif  // HAS_TCGEN05

__global__ __launch_bounds__(128, 1)
void gemm_kernel(const __nv_bfloat16* __restrict__ ah,
                 const __nv_bfloat16* __restrict__ al,
                 const __nv_bfloat16* __restrict__ xh,
                 const __nv_bfloat16* __restrict__ xl,
                 const float* __restrict__ rw,
                 const float* __restrict__ w,
                 const float* __restrict__ x,
                 float* __restrict__ out)
{
    extern __shared__ char smem[];
    const int tid = threadIdx.x;
    const int n0 = blockIdx.x * TN;
    const int b  = blockIdx.y;

#if HAS_TCGEN05
    (void)rw; (void)w; (void)x;
    const uint32_t smem_base = smem_u32(smem);
    uint32_t full[NSTAGE], mmad[NSTAGE];
#pragma unroll
    for (int s = 0; s < NSTAGE; s++) {
        full[s] = smem_base + 8 + 8 * s;
        mmad[s] = smem_base + 32 + 8 * s;
    }
    const uint32_t mb_done = smem_base + 56;

    if ((tid >> 5) == 0) TCGEN05_ALLOC(smem_base, 512);
    if (tid == 0) {
#pragma unroll
        for (int s = 0; s < NSTAGE; s++) {
            MBARRIER_INIT(full[s], 1);
            MBARRIER_INIT(mmad[s], 1);
        }
        MBARRIER_INIT(mb_done, 1);
    }
    if ((tid >> 5) == 0) TCGEN05_RELINQ();
    __syncthreads();

    uint32_t tmem_base;
    asm volatile("ld.shared.b32 %0, [%1];" : "=r"(tmem_base) : "r"(smem_base));

    if (tid == 0) {
        // GMEM bases (chunk-major SW64 layouts)
        const char* gah = (const char*)ah + (size_t)b * NCHUNK * AT_BYTES;
        const char* gal = (const char*)al + (size_t)b * NCHUNK * AT_BYTES;
        const char* gxh = (const char*)xh + ((size_t)b * NCHUNK * HW + n0) * 64;
        const char* gxl = (const char*)xl + ((size_t)b * NCHUNK * HW + n0) * 64;
        const size_t x_cstride = (size_t)HW * 64;

        // prologue: load chunks 0..2
#pragma unroll
        for (int c = 0; c < NSTAGE; c++) {
            const uint32_t stg = smem_base + SM_STAGE0 + c * STAGE_BYTES;
            MBARRIER_EXPECT_TX(full[c], STAGE_BYTES);
            BULK_G2S(stg,                          gah + (size_t)c * AT_BYTES, AT_BYTES, full[c]);
            BULK_G2S(stg + AT_BYTES,               gal + (size_t)c * AT_BYTES, AT_BYTES, full[c]);
            BULK_G2S(stg + 2 * AT_BYTES,           gxh + (size_t)c * x_cstride, XT_BYTES, full[c]);
            BULK_G2S(stg + 2 * AT_BYTES + XT_BYTES, gxl + (size_t)c * x_cstride, XT_BYTES, full[c]);
        }

        for (int c = 0; c < NCHUNK; c++) {
            const int s = c % NSTAGE;
            const int par = (c / NSTAGE) & 1;
            MBARRIER_WAIT_PARITY(full[s], par);

            const uint32_t stg = smem_base + SM_STAGE0 + s * STAGE_BYTES;
            const uint64_t dah = MAKE_DESC(stg);
            const uint64_t dal = MAKE_DESC(stg + AT_BYTES);
            const uint64_t dxh = MAKE_DESC(stg + 2 * AT_BYTES);
            const uint64_t dxl = MAKE_DESC(stg + 2 * AT_BYTES + XT_BYTES);
#pragma unroll
            for (int t = 0; t < 3; t++) {
                const uint32_t d  = tmem_base + t * TN;
                const uint64_t at = (uint64_t)t * 512;   // 128 rows * 64B / 16
                // hi*hi
                mma_f16_ss(d, dah + at,     dxh,     IDESC, c > 0 ? 1u : 0u);
                mma_f16_ss(d, dah + at + 2, dxh + 2, IDESC, 1u);
                // lo*hi
                mma_f16_ss(d, dal + at,     dxh,     IDESC, 1u);
                mma_f16_ss(d, dal + at + 2, dxh + 2, IDESC, 1u);
                // hi*lo
                mma_f16_ss(d, dah + at,     dxl,     IDESC, 1u);
                mma_f16_ss(d, dah + at + 2, dxl + 2, IDESC, 1u);
            }

            if (c == NCHUNK - 1) {
                TCGEN05_COMMIT(mb_done);
            } else {
                TCGEN05_COMMIT(mmad[s]);
                if (c + NSTAGE < NCHUNK) {
                    MBARRIER_WAIT_PARITY(mmad[s], par);
                    MBARRIER_EXPECT_TX(full[s], STAGE_BYTES);
                    const size_t co = (size_t)(c + NSTAGE);
                    BULK_G2S(stg,                           gah + co * AT_BYTES, AT_BYTES, full[s]);
                    BULK_G2S(stg + AT_BYTES,                gal + co * AT_BYTES, AT_BYTES, full[s]);
                    BULK_G2S(stg + 2 * AT_BYTES,            gxh + co * x_cstride, XT_BYTES, full[s]);
                    BULK_G2S(stg + 2 * AT_BYTES + XT_BYTES, gxl + co * x_cstride, XT_BYTES, full[s]);
                }
            }
        }
    }

    // ---- epilogue (all 4 warps): 3 M-tiles x 112 cols ----
    MBARRIER_WAIT_PARITY(mb_done, 0);
    TCGEN05_FENCE_AFTER();

    const int wid = tid >> 5, lid = tid & 31;
    uint32_t r[32];
#pragma unroll
    for (int t = 0; t < 3; t++) {
        const int m = t * 128 + wid * 32 + lid;
        float* orow = out + ((size_t)b * COUT + m) * HW + n0;
        const uint32_t tb = tmem_base + t * TN;

        LDTM_X32(r, tb);
        TCGEN05_WAIT_LD();
#pragma unroll
        for (int q = 0; q < 8; q++)
            *reinterpret_cast<float4*>(orow + q * 4) =
                make_float4(__uint_as_float(r[q*4]), __uint_as_float(r[q*4+1]),
                            __uint_as_float(r[q*4+2]), __uint_as_float(r[q*4+3]));
        LDTM_X32(r, tb + 32);
        TCGEN05_WAIT_LD();
#pragma unroll
        for (int q = 0; q < 8; q++)
            *reinterpret_cast<float4*>(orow + 32 + q * 4) =
                make_float4(__uint_as_float(r[q*4]), __uint_as_float(r[q*4+1]),
                            __uint_as_float(r[q*4+2]), __uint_as_float(r[q*4+3]));
        LDTM_X32(r, tb + 64);
        TCGEN05_WAIT_LD();
#pragma unroll
        for (int q = 0; q < 8; q++)
            *reinterpret_cast<float4*>(orow + 64 + q * 4) =
                make_float4(__uint_as_float(r[q*4]), __uint_as_float(r[q*4+1]),
                            __uint_as_float(r[q*4+2]), __uint_as_float(r[q*4+3]));
        LDTM_X16(r, tb + 96);
        TCGEN05_WAIT_LD();
#pragma unroll
        for (int q = 0; q < 4; q++)
            *reinterpret_cast<float4*>(orow + 96 + q * 4) =
                make_float4(__uint_as_float(r[q*4]), __uint_as_float(r[q*4+1]),
                            __uint_as_float(r[q*4+2]), __uint_as_float(r[q*4+3]));
    }

    TCGEN05_FENCE_BEFORE();
    __syncthreads();
    if ((tid >> 5) == 0) TCGEN05_DEALLOC(tmem_base, 512);

#else  // ---------- SIMT fallback (compute_103 pass only; never executes) ----
    (void)ah; (void)al; (void)xh; (void)xl; (void)smem;
    // Naive but correct: out[b,o,n] = sum_k (sum_e rw[b,e]*w[e,o,k]) * x[b,k,n]
    for (int idx = tid; idx < COUT * TN; idx += 128) {
        const int o = idx / TN;
        const int n = n0 + idx % TN;
        float acc = 0.f;
        for (int k = 0; k < CIN; k++) {
            float a = 0.f;
#pragma unroll
            for (int e = 0; e < NEXP; e++)
                a = fmaf(rw[b * NEXP + e], w[(size_t)e * COUT * CIN + o * CIN + k], a);
            acc = fmaf(a, x[(size_t)b * CIN * HW + (size_t)k * HW + n], acc);
        }
        out[((size_t)b * COUT + o) * HW + n] = acc;
    }
#endif
}

// ---------------------------------------------------------------------------
extern "C" void kernel_launch(void* const* d_in, const int* in_sizes, int n_in,
                              void* d_out, int out_size)
{
    const float* x  = (const float*)d_in[0];
    const float* rw = (const float*)d_in[1];
    const float* w  = (const float*)d_in[2];
    float* out = (float*)d_out;

    __nv_bfloat16 *ah, *al, *xh, *xl;
    cudaGetSymbolAddress((void**)&ah, g_a_hi);
    cudaGetSymbolAddress((void**)&al, g_a_lo);
    cudaGetSymbolAddress((void**)&xh, g_x_hi);
    cudaGetSymbolAddress((void**)&xl, g_x_lo);

    {
        dim3 grid((HW + 31) / 32, CIN / 32, BATCH);
        split_x_kernel<<<grid, dim3(32, 8)>>>(x, xh, xl);
    }
    {
        const int total = COUT * CIN;
        agg_kernel<<<(total + 255) / 256, 256>>>(rw, w, ah, al);
    }
    {
        cudaFuncSetAttribute(gemm_kernel, cudaFuncAttributeMaxDynamicSharedMemorySize, SM_TOTAL);
        dim3 grid(HW / TN, BATCH);   // 7 x 64 = 448 CTAs
        gemm_kernel<<<grid, 128, SM_TOTAL>>>(ah, al, xh, xl, rw, w, x, out);
    }
}